// round 15
// baseline (speedup 1.0000x reference)
#include <cuda_runtime.h>
#include <cuda_fp16.h>

// DilationLayerExtSE: out[b,c,h,w] = max_{di,dj in 5x5}( zeropad2(x)[h+di,w+dj] + w[b,c,di,dj] ) + bias[b,c]
// x [8,128,128,128] f32. stride=1, pad=2.
//
// R15: occupancy attack. Same half-plane fp16 smem tile as R12, but the fold
// is restructured so the register live-set shrinks ~60 -> ~28:
//   - weights live in SMEM (5 broadcast LDS per (oh,di)), not 25 registers
//   - direct per-output-row fold: acc is 4 half2, no 5-row in-flight window
//   - oh is a REAL loop (I$ footprint ~5KB, fits L0)
// __launch_bounds__(128, 12): 12 blocks/SM = 48 warps (75% theoretical
// occupancy vs 50% before). smem 18.5KB x 12 = 222KB <= 228KB carveout.
// Zero padding: OOB gives x=0 (reference zero-pads BEFORE +w).
// Layout: global col c <-> tile half index c+4 (left halo halves 2,3).

#define H_DIM 128
#define W_DIM 128
#define TROWS 68            // 64 output rows + 2 halo each side
#define TPITCH 136          // halves per tile row
#define TP2 (TPITCH / 2)    // 68 half2 per row

__device__ __forceinline__ unsigned h2u(__half2 v) {
    return *reinterpret_cast<unsigned*>(&v);
}
__device__ __forceinline__ __half2 u2h(unsigned v) {
    return *reinterpret_cast<__half2*>(&v);
}
// (a.y, b.x) — one PRMT
__device__ __forceinline__ __half2 h2shift(__half2 a, __half2 b) {
    return u2h(__byte_perm(h2u(a), h2u(b), 0x5432));
}

__global__ __launch_bounds__(128, 12)
void dilation_kernel(const float* __restrict__ x,
                     const float* __restrict__ wgt,
                     const float* __restrict__ bias,
                     float* __restrict__ out) {
    __shared__ __half2 s_tile[TROWS * TP2];          // 18496 B
    __shared__ __half2 s_w[25];                      // bias-folded weights

    const int blk   = blockIdx.x;            // 0..2047
    const int plane = blk >> 1;              // b*C + c
    const int half  = blk & 1;
    const int tid   = threadIdx.x;
    const int cg    = tid & 15;              // column group 0..15 (8 cols)
    const int strip = tid >> 4;              // 0..7 (8 rows each)
    const int colbase = cg << 3;

    const float* __restrict__ xpl = x   + (size_t)plane * (H_DIM * W_DIM);
    float*       __restrict__ op  = out + (size_t)plane * (H_DIM * W_DIM) + colbase;
    const float* __restrict__ wp  = wgt + plane * 25;

    // weights (bias folded, single rounding) -> smem
    if (tid < 25) {
        const float b = __ldg(&bias[plane]);
        s_w[tid] = __float2half2_rn(__ldg(&wp[tid]) + b);
    }

    // ---- stage tile: vectorized zero-fill, then overwrite valid region ----
    {
        int4* zp = reinterpret_cast<int4*>(s_tile);
        const int4 z4 = make_int4(0, 0, 0, 0);
        for (int i = tid; i < (TROWS * TPITCH * 2) / 16; i += 128) zp[i] = z4;
    }
    __syncthreads();

    const int rtile0 = half * 64 - 2;        // global row of tile row 0
#pragma unroll
    for (int i = tid; i < TROWS * 32; i += 128) {
        const int row = i >> 5;
        const int g   = i & 31;              // float4 group, cols 4g..4g+3
        const int r   = rtile0 + row;
        if ((unsigned)r < (unsigned)H_DIM) {
            const float4 v = __ldg(reinterpret_cast<const float4*>(xpl + r * W_DIM + g * 4));
            const int bi = row * TP2 + 2 + g * 2;  // half2 index
            s_tile[bi]     = __floats2half2_rn(v.x, v.y);
            s_tile[bi + 1] = __floats2half2_rn(v.z, v.w);
        }
    }
    __syncthreads();

    // ---- fold: direct per-output-row, weights from smem ----
    // pair j of tile row tr at half idx: tr*TPITCH + 2 + colbase + j
    const __half* s_base = reinterpret_cast<const __half*>(s_tile)
                         + strip * 8 * TPITCH + 2 + colbase;
    float* orow = op + (size_t)(half * 64 + strip * 8) * W_DIM;

#pragma unroll 1
    for (int oh = 0; oh < 8; ++oh) {
        __half2 a[4];
        const __half* rbase = s_base + oh * TPITCH;

#pragma unroll
        for (int di = 0; di < 5; ++di) {
            const __half* rp = rbase + di * TPITCH;
            const __half2 w0 = s_w[di * 5 + 0];
            const __half2 w1 = s_w[di * 5 + 1];
            const __half2 w2 = s_w[di * 5 + 2];
            const __half2 w3 = s_w[di * 5 + 3];
            const __half2 w4 = s_w[di * 5 + 4];

            __half2 pairs[11];
#pragma unroll
            for (int i = 0; i < 6; ++i)
                pairs[2 * i] = *reinterpret_cast<const __half2*>(rp + 2 * i);
#pragma unroll
            for (int i = 0; i < 5; ++i)
                pairs[2 * i + 1] = h2shift(pairs[2 * i], pairs[2 * i + 2]);

#pragma unroll
            for (int p = 0; p < 4; ++p) {
                const __half2 m01 = __hmax2(__hadd2(pairs[2 * p],     w0),
                                            __hadd2(pairs[2 * p + 1], w1));
                const __half2 m23 = __hmax2(__hadd2(pairs[2 * p + 2], w2),
                                            __hadd2(pairs[2 * p + 3], w3));
                const __half2 m4  = __hadd2(pairs[2 * p + 4], w4);
                const __half2 m   = __hmax2(__hmax2(m01, m23), m4);
                a[p] = (di == 0) ? m : __hmax2(a[p], m);
            }
        }

        const float2 f0 = __half22float2(a[0]);
        const float2 f1 = __half22float2(a[1]);
        const float2 f2 = __half22float2(a[2]);
        const float2 f3 = __half22float2(a[3]);
        *reinterpret_cast<float4*>(orow)     = make_float4(f0.x, f0.y, f1.x, f1.y);
        *reinterpret_cast<float4*>(orow + 4) = make_float4(f2.x, f2.y, f3.x, f3.y);
        orow += W_DIM;
    }
}

extern "C" void kernel_launch(void* const* d_in, const int* in_sizes, int n_in,
                              void* d_out, int out_size) {
    (void)in_sizes; (void)n_in; (void)out_size;
    const float* x    = (const float*)d_in[0];   // [8,128,128,128]
    const float* wgt  = (const float*)d_in[1];   // [8,128,5,5]
    const float* bias = (const float*)d_in[2];   // [8,128]
    float* out = (float*)d_out;                  // [8,128,128,128]

    dilation_kernel<<<2048, 128>>>(x, wgt, bias, out);
}

// round 16
// speedup vs baseline: 1.7708x; 1.7708x over previous
#include <cuda_runtime.h>
#include <cuda_fp16.h>

// DilationLayerExtSE: out[b,c,h,w] = max_{di,dj in 5x5}( zeropad2(x)[h+di,w+dj] + w[b,c,di,dj] ) + bias[b,c]
// x [8,128,128,128] f32. stride=1, pad=2.
//
// R16 = R12 (half-plane fp16 smem tile, HADD2/HMAX2 tree fold, full STS.128
//            zero-fill, 5-row in-flight acc window) with ONE change:
//   tile layout shifted so global col c sits at half index c+2. A thread's
//   pair base (col colbase-2 -> half colbase) is then 16B-aligned, so the
//   6 LDS.32 per tile row become LDS.128 (pairs 0,2,4,6) + LDS.64 (pairs
//   8,10): 3x fewer shared-memory ops in the hot loop.
// Block = half plane: 2048 x 128 thr; thread = 8 cols x 8 rows, 12 fold
// iterations. Bias folded into fp16 weights. Zero padding: OOB gives x=0
// (reference zero-pads BEFORE +w).
// Layout: col c <-> half c+2; left halo (cols -2,-1) at halves 0,1 (cg0
// only); right halo (cols 128,129) at halves 130,131; TPITCH=136 for 16B
// row alignment.

#define H_DIM 128
#define W_DIM 128
#define TROWS 68            // 64 output rows + 2 halo each side
#define TPITCH 136          // halves per tile row (272 B, 16B-aligned)
#define TP2 (TPITCH / 2)    // 68 half2 per row

__device__ __forceinline__ unsigned h2u(__half2 v) {
    return *reinterpret_cast<unsigned*>(&v);
}
__device__ __forceinline__ __half2 u2h(unsigned v) {
    return *reinterpret_cast<__half2*>(&v);
}
// (a.y, b.x) — one PRMT
__device__ __forceinline__ __half2 h2shift(__half2 a, __half2 b) {
    return u2h(__byte_perm(h2u(a), h2u(b), 0x5432));
}

__global__ __launch_bounds__(128, 8)
void dilation_kernel(const float* __restrict__ x,
                     const float* __restrict__ wgt,
                     const float* __restrict__ bias,
                     float* __restrict__ out) {
    __shared__ __half2 s_tile[TROWS * TP2];          // 18496 B

    const int blk   = blockIdx.x;            // 0..2047
    const int plane = blk >> 1;              // b*C + c
    const int half  = blk & 1;
    const int tid   = threadIdx.x;
    const int cg    = tid & 15;              // column group 0..15 (8 cols)
    const int strip = tid >> 4;              // 0..7 (8 rows each)
    const int colbase = cg << 3;

    const float* __restrict__ xpl = x   + (size_t)plane * (H_DIM * W_DIM);
    float*       __restrict__ op  = out + (size_t)plane * (H_DIM * W_DIM) + colbase;
    const float* __restrict__ wp  = wgt + plane * 25;
    const float b = __ldg(&bias[plane]);

    // fp16 weights with bias folded (single rounding of w+b)
    __half2 wh[25];
#pragma unroll
    for (int k = 0; k < 25; ++k) wh[k] = __float2half2_rn(__ldg(&wp[k]) + b);

    // ---- stage tile: vectorized zero-fill, then overwrite valid region ----
    {
        int4* zp = reinterpret_cast<int4*>(s_tile);
        const int4 z4 = make_int4(0, 0, 0, 0);
        for (int i = tid; i < (TROWS * TPITCH * 2) / 16; i += 128) zp[i] = z4;
    }
    __syncthreads();

    const int rtile0 = half * 64 - 2;        // global row of tile row 0
    // valid fill: global col c -> half index c+2; float4 group g (cols
    // 4g..4g+3) -> half2 indices (1+2g), (2+2g)
#pragma unroll
    for (int i = tid; i < TROWS * 32; i += 128) {
        const int row = i >> 5;
        const int g   = i & 31;
        const int r   = rtile0 + row;
        if ((unsigned)r < (unsigned)H_DIM) {
            const float4 v = __ldg(reinterpret_cast<const float4*>(xpl + r * W_DIM + g * 4));
            const int bi = row * TP2 + 1 + g * 2;  // half2 index
            s_tile[bi]     = __floats2half2_rn(v.x, v.y);
            s_tile[bi + 1] = __floats2half2_rn(v.z, v.w);
        }
    }
    __syncthreads();

    // ---- fold loop: 2 LDS (128+64) per row, no predicates ----
    // pair j (cols colbase-2+j, colbase-1+j) at half idx:
    //   (strip*8+t)*TPITCH + colbase + j      (base 16B-aligned)
    const __half* s_base = reinterpret_cast<const __half*>(s_tile)
                         + strip * 8 * TPITCH + colbase;

    __half2 acc[5][4];                       // 5 in-flight output rows x 4 pairs

#pragma unroll
    for (int t = 0; t < 12; ++t) {
        const __half* rp = s_base + t * TPITCH;

        __half2 pairs[11];
        {
            const uint4 u0 = *reinterpret_cast<const uint4*>(rp);      // pairs 0,2,4,6
            const uint2 u1 = *reinterpret_cast<const uint2*>(rp + 8);  // pairs 8,10
            pairs[0]  = u2h(u0.x); pairs[2]  = u2h(u0.y);
            pairs[4]  = u2h(u0.z); pairs[6]  = u2h(u0.w);
            pairs[8]  = u2h(u1.x); pairs[10] = u2h(u1.y);
        }
#pragma unroll
        for (int i = 0; i < 5; ++i)
            pairs[2 * i + 1] = h2shift(pairs[2 * i], pairs[2 * i + 2]);

        // fold into in-flight outputs oh = t-di (weight row di), tree max
#pragma unroll
        for (int di = 0; di < 5; ++di) {
            const int oh = t - di;
            if (oh < 0 || oh > 7) continue;  // compile-time pruned
            __half2* a = acc[oh % 5];
            const __half2* w = &wh[di * 5];
#pragma unroll
            for (int p = 0; p < 4; ++p) {
                const __half2 m01 = __hmax2(__hadd2(pairs[2 * p],     w[0]),
                                            __hadd2(pairs[2 * p + 1], w[1]));
                const __half2 m23 = __hmax2(__hadd2(pairs[2 * p + 2], w[2]),
                                            __hadd2(pairs[2 * p + 3], w[3]));
                const __half2 m4  = __hadd2(pairs[2 * p + 4], w[4]);
                const __half2 m   = __hmax2(__hmax2(m01, m23), m4);
                a[p] = (di == 0) ? m : __hmax2(a[p], m);
            }
        }

        // output row oh = t-4 complete: convert to fp32, store (bias already in)
        if (t >= 4) {
            const int oh = t - 4;
            const __half2* a = acc[oh % 5];
            float* orow = op + (size_t)(half * 64 + strip * 8 + oh) * W_DIM;
            const float2 f0 = __half22float2(a[0]);
            const float2 f1 = __half22float2(a[1]);
            const float2 f2 = __half22float2(a[2]);
            const float2 f3 = __half22float2(a[3]);
            *reinterpret_cast<float4*>(orow)     = make_float4(f0.x, f0.y, f1.x, f1.y);
            *reinterpret_cast<float4*>(orow + 4) = make_float4(f2.x, f2.y, f3.x, f3.y);
        }
    }
}

extern "C" void kernel_launch(void* const* d_in, const int* in_sizes, int n_in,
                              void* d_out, int out_size) {
    (void)in_sizes; (void)n_in; (void)out_size;
    const float* x    = (const float*)d_in[0];   // [8,128,128,128]
    const float* wgt  = (const float*)d_in[1];   // [8,128,5,5]
    const float* bias = (const float*)d_in[2];   // [8,128]
    float* out = (float*)d_out;                  // [8,128,128,128]

    dilation_kernel<<<2048, 128>>>(x, wgt, bias, out);
}